// round 1
// baseline (speedup 1.0000x reference)
#include <cuda_runtime.h>

#define NN 50000
#define EE 800000
#define EP 850000   /* EE + NN self loops */
#define FDIM 64     /* HEADS*HID */
#define OUTC 40

// ---------------- device scratch (no allocation allowed) ----------------
__device__ int   g_is64;
__device__ int   g_src[EE];
__device__ int   g_dst[EE];
__device__ int   g_deg[NN];
__device__ int   g_off[NN];
__device__ int   g_cur[NN];
__device__ int   g_csr_src[EP];
__device__ int   g_bsums[64];
__device__ float g_bufA[NN * FDIM];
__device__ float g_bufB[NN * FDIM];
__device__ float g_as[NN * 4];
__device__ float g_ad[NN * 4];
__device__ float g_ae[(size_t)EP * 4];
__device__ float g_stats0[2 * FDIM];
__device__ float g_stats1[2 * FDIM];
__device__ float g_scale0[FDIM], g_shift0[FDIM], g_scale1[FDIM], g_shift1[FDIM];

// ---------------- dtype detection: int64 edge_index has zero high words ----
__global__ void k_detect(const unsigned* __restrict__ w) {
    __shared__ int nz;
    if (threadIdx.x == 0) nz = 0;
    __syncthreads();
    if (w[2 * threadIdx.x + 1] != 0u) atomicAdd(&nz, 1);
    __syncthreads();
    if (threadIdx.x == 0) g_is64 = (nz == 0) ? 1 : 0;
}

__global__ void k_convert(const void* __restrict__ ei) {
    int i = blockIdx.x * blockDim.x + threadIdx.x;
    if (i >= EE) return;
    if (g_is64) {
        const long long* p = (const long long*)ei;
        g_src[i] = (int)p[i];
        g_dst[i] = (int)p[EE + i];
    } else {
        const int* p = (const int*)ei;
        g_src[i] = p[i];
        g_dst[i] = p[EE + i];
    }
}

__global__ void k_zero() {
    int i = blockIdx.x * blockDim.x + threadIdx.x;
    if (i < NN) { g_deg[i] = 0; g_cur[i] = 0; }
    if (i < 2 * FDIM) { g_stats0[i] = 0.f; g_stats1[i] = 0.f; }
}

__global__ void k_count() {
    int i = blockIdx.x * blockDim.x + threadIdx.x;
    if (i >= EP) return;
    int d = (i < EE) ? g_dst[i] : (i - EE);
    atomicAdd(&g_deg[d], 1);
}

// ---------------- exclusive scan of g_deg -> g_off ----------------
__global__ void k_scan1() {
    __shared__ int sm[1024];
    int i = blockIdx.x * 1024 + threadIdx.x;
    int v = (i < NN) ? g_deg[i] : 0;
    sm[threadIdx.x] = v;
    __syncthreads();
    for (int d = 1; d < 1024; d <<= 1) {
        int t = (threadIdx.x >= d) ? sm[threadIdx.x - d] : 0;
        __syncthreads();
        sm[threadIdx.x] += t;
        __syncthreads();
    }
    if (i < NN) g_off[i] = sm[threadIdx.x] - v;
    if (threadIdx.x == 1023) g_bsums[blockIdx.x] = sm[1023];
}

__global__ void k_scan2(int nb) {
    if (threadIdx.x == 0) {
        int run = 0;
        for (int b = 0; b < nb; b++) { int t = g_bsums[b]; g_bsums[b] = run; run += t; }
    }
}

__global__ void k_scan3() {
    int i = blockIdx.x * 1024 + threadIdx.x;
    if (i < NN) g_off[i] += g_bsums[blockIdx.x];
}

__global__ void k_fill() {
    int i = blockIdx.x * blockDim.x + threadIdx.x;
    if (i >= EP) return;
    int d, s;
    if (i < EE) { d = g_dst[i]; s = g_src[i]; }
    else        { d = i - EE;   s = i - EE;   }
    int slot = g_off[d] + atomicAdd(&g_cur[d], 1);
    g_csr_src[slot] = s;
}

// ---------------- GEMM: Y[n,o] = sum_k BN(X[n,k]) * W[o,k] ----------------
template<int FIN, int FOUT>
__global__ void k_gemm(const float* __restrict__ X, const float* __restrict__ W,
                       const float* __restrict__ scale, const float* __restrict__ shift,
                       float* __restrict__ Y) {
    __shared__ float Ws[FIN * FOUT];   // [k*FOUT + o]
    __shared__ float xs[4][FIN];
    for (int i = threadIdx.x; i < FIN * FOUT; i += 256) {
        int o = i / FIN, k = i - o * FIN;
        Ws[k * FOUT + o] = W[i];
    }
    int rowBase = blockIdx.x * 64;
    for (int r0 = 0; r0 < 64; r0 += 4) {
        __syncthreads();
        for (int i = threadIdx.x; i < 4 * FIN; i += 256) {
            int r = i / FIN, k = i - r * FIN;
            int n = rowBase + r0 + r;
            float v = 0.f;
            if (n < NN) {
                v = X[n * FIN + k];
                if (scale) v = v * scale[k] + shift[k];
            }
            xs[r][k] = v;
        }
        __syncthreads();
        if (threadIdx.x < 4 * FOUT) {
            int o = threadIdx.x % FOUT, r = threadIdx.x / FOUT;
            int n = rowBase + r0 + r;
            if (n < NN) {
                float acc = 0.f;
                #pragma unroll 8
                for (int k = 0; k < FIN; k++) acc += xs[r][k] * Ws[k * FOUT + o];
                Y[n * FOUT + o] = acc;
            }
        }
    }
}

// ---------------- per-node attention coefficients ----------------
template<int H, int C>
__global__ void k_alpha(const float* __restrict__ Hl, const float* __restrict__ av_s,
                        const float* __restrict__ av_d) {
    int gw = (blockIdx.x * blockDim.x + threadIdx.x) >> 5;
    int lane = threadIdx.x & 31;
    if (gw >= NN) return;
    float ss[4], sd[4];
    #pragma unroll
    for (int h = 0; h < 4; h++) { ss[h] = 0.f; sd[h] = 0.f; }
    for (int ch = lane; ch < H * C; ch += 32) {
        int h = ch / C;
        float v = Hl[gw * H * C + ch];
        ss[h] += v * av_s[ch];
        sd[h] += v * av_d[ch];
    }
    #pragma unroll
    for (int h = 0; h < H; h++)
        for (int s = 16; s; s >>= 1) {
            ss[h] += __shfl_xor_sync(0xffffffffu, ss[h], s);
            sd[h] += __shfl_xor_sync(0xffffffffu, sd[h], s);
        }
    if (lane == 0) {
        #pragma unroll
        for (int h = 0; h < H; h++) { g_as[gw * H + h] = ss[h]; g_ad[gw * H + h] = sd[h]; }
    }
}

// ---------------- warp-per-node segment softmax + weighted aggregation ------
template<int H, int C>
__global__ void k_agg(const float* __restrict__ Hl, const float* __restrict__ bias,
                      float* __restrict__ Y) {
    const int HC = H * C;
    int gw = (blockIdx.x * blockDim.x + threadIdx.x) >> 5;
    int lane = threadIdx.x & 31;
    if (gw >= NN) return;
    int off = g_off[gw], deg = g_deg[gw];

    float ad[4];
    #pragma unroll
    for (int h = 0; h < H; h++) ad[h] = g_ad[gw * H + h];

    // pass 1: logits + per-head max
    float mx[4];
    #pragma unroll
    for (int h = 0; h < H; h++) mx[h] = -1e30f;
    for (int i = lane; i < deg; i += 32) {
        int s = g_csr_src[off + i];
        #pragma unroll
        for (int h = 0; h < H; h++) {
            float l = g_as[s * H + h] + ad[h];
            l = l > 0.f ? l : 0.2f * l;
            g_ae[(size_t)(off + i) * H + h] = l;
            mx[h] = fmaxf(mx[h], l);
        }
    }
    #pragma unroll
    for (int h = 0; h < H; h++)
        for (int s = 16; s; s >>= 1)
            mx[h] = fmaxf(mx[h], __shfl_xor_sync(0xffffffffu, mx[h], s));

    // pass 2: exp + sum
    float sm[4];
    #pragma unroll
    for (int h = 0; h < H; h++) sm[h] = 0.f;
    for (int i = lane; i < deg; i += 32) {
        #pragma unroll
        for (int h = 0; h < H; h++) {
            float e = __expf(g_ae[(size_t)(off + i) * H + h] - mx[h]);
            g_ae[(size_t)(off + i) * H + h] = e;
            sm[h] += e;
        }
    }
    #pragma unroll
    for (int h = 0; h < H; h++)
        for (int s = 16; s; s >>= 1)
            sm[h] += __shfl_xor_sync(0xffffffffu, sm[h], s);
    float rs[4];
    #pragma unroll
    for (int h = 0; h < H; h++) rs[h] = 1.f / (sm[h] + 1e-16f);

    // pass 3: weighted gather-accumulate; lane owns channels (lane, lane+32)
    const int ch0 = lane, ch1 = lane + 32;
    float acc0 = 0.f, acc1 = 0.f;
    for (int i0 = 0; i0 < deg; i0 += 32) {
        int myi = i0 + lane;
        int s_l = 0;
        float an[4];
        #pragma unroll
        for (int h = 0; h < 4; h++) an[h] = 0.f;
        if (myi < deg) {
            s_l = g_csr_src[off + myi];
            #pragma unroll
            for (int h = 0; h < H; h++) an[h] = g_ae[(size_t)(off + myi) * H + h] * rs[h];
        }
        int cnt = min(32, deg - i0);
        for (int j = 0; j < cnt; j++) {
            int s = __shfl_sync(0xffffffffu, s_l, j);
            float c0, c1;
            if (H == 4) {   // C==16: ch0 head = lane/16 in {0,1}; ch1 head in {2,3}
                float a0 = __shfl_sync(0xffffffffu, an[0], j);
                float a1 = __shfl_sync(0xffffffffu, an[1], j);
                float a2 = __shfl_sync(0xffffffffu, an[2], j);
                float a3 = __shfl_sync(0xffffffffu, an[3], j);
                c0 = (lane < 16) ? a0 : a1;
                c1 = (lane < 16) ? a2 : a3;
            } else {
                float a0 = __shfl_sync(0xffffffffu, an[0], j);
                c0 = a0; c1 = a0;
            }
            acc0 += Hl[s * HC + ch0] * c0;
            if (ch1 < HC) acc1 += Hl[s * HC + ch1] * c1;
        }
    }
    Y[gw * HC + ch0] = acc0 + bias[ch0];
    if (ch1 < HC) Y[gw * HC + ch1] = acc1 + bias[ch1];
}

// ---------------- batch norm ----------------
__global__ void k_bnstats(const float* __restrict__ Y, float* __restrict__ st) {
    int c = threadIdx.x & 63;
    int rg = blockIdx.x * (blockDim.x >> 6) + (threadIdx.x >> 6);
    int stride = gridDim.x * (blockDim.x >> 6);
    float s = 0.f, q = 0.f;
    for (int n = rg; n < NN; n += stride) {
        float v = Y[n * FDIM + c];
        s += v; q += v * v;
    }
    atomicAdd(&st[c], s);
    atomicAdd(&st[FDIM + c], q);
}

__global__ void k_bnfin(const float* __restrict__ st, const float* __restrict__ g,
                        const float* __restrict__ b, float* __restrict__ sc,
                        float* __restrict__ sh) {
    int c = threadIdx.x;
    if (c < FDIM) {
        float mean = st[c] * (1.f / NN);
        float var  = st[FDIM + c] * (1.f / NN) - mean * mean;
        float s = g[c] * rsqrtf(var + 1e-5f);
        sc[c] = s;
        sh[c] = b[c] - mean * s;
    }
}

// ---------------- log_softmax + output ----------------
__global__ void k_lsm(const float* __restrict__ emb, float* __restrict__ out, int writeEmb) {
    int gw = (blockIdx.x * blockDim.x + threadIdx.x) >> 5;
    int lane = threadIdx.x & 31;
    if (gw >= NN) return;
    float v0 = emb[gw * OUTC + lane];
    float v1 = (lane < 8) ? emb[gw * OUTC + lane + 32] : -1e30f;
    float m = fmaxf(v0, v1);
    for (int s = 16; s; s >>= 1) m = fmaxf(m, __shfl_xor_sync(0xffffffffu, m, s));
    float e = expf(v0 - m) + ((lane < 8) ? expf(v1 - m) : 0.f);
    for (int s = 16; s; s >>= 1) e += __shfl_xor_sync(0xffffffffu, e, s);
    float lse = m + logf(e);
    out[gw * OUTC + lane] = v0 - lse;
    if (lane < 8) out[gw * OUTC + lane + 32] = v1 - lse;
    if (writeEmb) {
        out[NN * OUTC + gw * OUTC + lane] = v0;
        if (lane < 8) out[NN * OUTC + gw * OUTC + lane + 32] = v1;
    }
}

// ---------------- launcher ----------------
extern "C" void kernel_launch(void* const* d_in, const int* in_sizes, int n_in,
                              void* d_out, int out_size) {
    const float* x   = (const float*)d_in[0];
    const void*  ei  = d_in[1];
    const float* W0  = (const float*)d_in[2];
    const float* as0 = (const float*)d_in[3];
    const float* ad0 = (const float*)d_in[4];
    const float* b0  = (const float*)d_in[5];
    const float* W1  = (const float*)d_in[6];
    const float* as1 = (const float*)d_in[7];
    const float* ad1 = (const float*)d_in[8];
    const float* b1  = (const float*)d_in[9];
    const float* W2  = (const float*)d_in[10];
    const float* as2 = (const float*)d_in[11];
    const float* ad2 = (const float*)d_in[12];
    const float* b2  = (const float*)d_in[13];
    const float* g0  = (const float*)d_in[14];
    const float* bt0 = (const float*)d_in[15];
    const float* g1  = (const float*)d_in[16];
    const float* bt1 = (const float*)d_in[17];
    float* out = (float*)d_out;

    float *bufA, *bufB, *st0, *st1, *sc0, *sh0, *sc1, *sh1;
    cudaGetSymbolAddress((void**)&bufA, g_bufA);
    cudaGetSymbolAddress((void**)&bufB, g_bufB);
    cudaGetSymbolAddress((void**)&st0, g_stats0);
    cudaGetSymbolAddress((void**)&st1, g_stats1);
    cudaGetSymbolAddress((void**)&sc0, g_scale0);
    cudaGetSymbolAddress((void**)&sh0, g_shift0);
    cudaGetSymbolAddress((void**)&sc1, g_scale1);
    cudaGetSymbolAddress((void**)&sh1, g_shift1);

    // ---- CSR build (every launch; graph-capturable, deterministic work) ----
    k_detect<<<1, 1024>>>((const unsigned*)ei);
    k_convert<<<(EE + 255) / 256, 256>>>(ei);
    k_zero<<<(NN + 255) / 256, 256>>>();
    k_count<<<(EP + 255) / 256, 256>>>();
    k_scan1<<<49, 1024>>>();
    k_scan2<<<1, 32>>>(49);
    k_scan3<<<49, 1024>>>();
    k_fill<<<(EP + 255) / 256, 256>>>();

    const int GEMM_BLOCKS = (NN + 63) / 64;
    const int NODE_BLOCKS = (NN + 7) / 8;   // warp per node, 8 warps/block

    // ---- layer 0: 128 -> 4x16 ----
    k_gemm<128, 64><<<GEMM_BLOCKS, 256>>>(x, W0, nullptr, nullptr, bufA);
    k_alpha<4, 16><<<NODE_BLOCKS, 256>>>(bufA, as0, ad0);
    k_agg<4, 16><<<NODE_BLOCKS, 256>>>(bufA, b0, bufB);
    k_bnstats<<<256, 256>>>(bufB, st0);
    k_bnfin<<<1, 64>>>(st0, g0, bt0, sc0, sh0);

    // ---- layer 1: 64 -> 4x16 (BN fused into GEMM load) ----
    k_gemm<64, 64><<<GEMM_BLOCKS, 256>>>(bufB, W1, sc0, sh0, bufA);
    k_alpha<4, 16><<<NODE_BLOCKS, 256>>>(bufA, as1, ad1);
    k_agg<4, 16><<<NODE_BLOCKS, 256>>>(bufA, b1, bufB);
    k_bnstats<<<256, 256>>>(bufB, st1);
    k_bnfin<<<1, 64>>>(st1, g1, bt1, sc1, sh1);

    // ---- layer 2: 64 -> 40, 1 head, concat=False (mean over 1 head = id) ----
    k_gemm<64, 40><<<GEMM_BLOCKS, 256>>>(bufB, W2, sc1, sh1, bufA);
    k_alpha<1, 40><<<NODE_BLOCKS, 256>>>(bufA, as2, ad2);
    k_agg<1, 40><<<NODE_BLOCKS, 256>>>(bufA, b2, bufB);

    int writeEmb = (out_size >= 2 * NN * OUTC) ? 1 : 0;
    k_lsm<<<NODE_BLOCKS, 256>>>(bufB, out, writeEmb);
}